// round 7
// baseline (speedup 1.0000x reference)
#include <cuda_runtime.h>
#include <cuda_fp16.h>

// Problem shape (fixed by the dataset)
#define BATCH 8
#define CHAN  3
#define HH    720
#define WW    1280
#define HW    (HH * WW)
#define NROWS (BATCH * HH)
#define NT    320
#define EPSV  1e-6f
#define K_LOG2 0.49978218f     // log2(1.414)

// flow_y == 0 -> 1-D row splat: pixel x hits bins floor(x-d) and floor(x-d)+1.
// Accumulate (c0,c1) and (c2,wsum) as two __half2 shared planes via f16x2
// shared atomics (4 ATOMS/pixel, payload floor).
//
// KEY CHANGE vs R3: cyclic pixel-to-lane mapping. Blocked mapping made warp
// atomic banks = (4*lane + k - d) mod 32 -> lanes {i,i+8,i+16,i+24} share a
// base bank (built-in 4-way conflict). Cyclic mapping gives banks
// (lane - d) mod 32: 32 distinct bases, random shifts, expected degree ~2.
// Scalar LDG.32/STG.32 with consecutive lanes keep identical wavefront cost.
__global__ __launch_bounds__(NT) void splat_kernel(
    const float* __restrict__ im,
    const float* __restrict__ disp,
    float* __restrict__ out)
{
    __shared__ __half2 sA[WW];   // (c0, c1) per bin
    __shared__ __half2 sB[WW];   // (c2, w ) per bin

    const int row = blockIdx.x;      // b*HH + y
    const int b   = row / HH;
    const int y   = row - b * HH;
    const int tid = threadIdx.x;

    // ---- zero both planes: 2*1280 half2 = 640 uint4, 2 per thread ----
    ((uint4*)sA)[tid] = make_uint4(0u, 0u, 0u, 0u);
    ((uint4*)sB)[tid] = make_uint4(0u, 0u, 0u, 0u);
    __syncthreads();

    const float* d_row  = disp + (size_t)row * WW;
    const float* im_row = im  + (size_t)b * CHAN * HW + (size_t)y * WW;
    float*       o_row  = out + (size_t)b * CHAN * HW + (size_t)y * WW;

    // ---- splat: cyclic mapping, pixel x = tid + 320k ----
    // batch the disp loads first (longest dependency chain: d -> addr -> atomic)
    float dd[4];
    #pragma unroll
    for (int k = 0; k < 4; k++) dd[k] = d_row[tid + NT * k];

    #pragma unroll
    for (int k = 0; k < 4; k++) {
        const int x = tid + NT * k;
        float d = dd[k];
        float w;
        asm("ex2.approx.f32 %0, %1;" : "=f"(w) : "f"(d * K_LOG2));
        float tx  = (float)x - d;
        int   x0  = __float2int_rd(tx);
        float fc  = tx - (float)x0;   // weight toward x0+1
        float wc  = w * fc;           // combined weight at x0+1
        float wa  = w - wc;           // combined weight at x0

        float v0 = im_row[x];
        float v1 = im_row[HW + x];
        float v2 = im_row[2 * HW + x];

        if ((unsigned)x0 < WW) {      // x0 in [x-21, x], may be negative
            atomicAdd(&sA[x0], __floats2half2_rn(v0 * wa, v1 * wa));
            atomicAdd(&sB[x0], __floats2half2_rn(v2 * wa, wa));
        }
        int x1 = x0 + 1;
        if ((unsigned)x1 < WW) {
            atomicAdd(&sA[x1], __floats2half2_rn(v0 * wc, v1 * wc));
            atomicAdd(&sB[x1], __floats2half2_rn(v2 * wc, wc));
        }
    }
    __syncthreads();

    // ---- normalize: uint4 reads from shared, float4 writes (tid-blocked) ----
    uint4 ua = ((const uint4*)sA)[tid];   // 4 pixels of (c0,c1)
    uint4 ub = ((const uint4*)sB)[tid];   // 4 pixels of (c2,w)
    const unsigned va[4] = {ua.x, ua.y, ua.z, ua.w};
    const unsigned vb[4] = {ub.x, ub.y, ub.z, ub.w};

    float4 r0, r1, r2;
    float* r0p = &r0.x; float* r1p = &r1.x; float* r2p = &r2.x;
    #pragma unroll
    for (int j = 0; j < 4; j++) {
        __half2 a  = *(const __half2*)&va[j];
        __half2 bb = *(const __half2*)&vb[j];
        float n0 = __low2float(a),  n1 = __high2float(a);
        float n2 = __low2float(bb), ws = __high2float(bb);
        float inv;
        asm("rcp.approx.f32 %0, %1;" : "=f"(inv) : "f"(fmaxf(ws, EPSV)));
        r0p[j] = n0 * inv;
        r1p[j] = n1 * inv;
        r2p[j] = n2 * inv;
    }
    ((float4*)o_row)[tid]            = r0;
    ((float4*)(o_row + HW))[tid]     = r1;
    ((float4*)(o_row + 2 * HW))[tid] = r2;
}

extern "C" void kernel_launch(void* const* d_in, const int* in_sizes, int n_in,
                              void* d_out, int out_size) {
    const float* im   = (const float*)d_in[0];   // [8,3,720,1280] fp32
    const float* disp = (const float*)d_in[1];   // [8,1,720,1280] fp32
    float* out = (float*)d_out;                  // [8,3,720,1280] fp32

    splat_kernel<<<NROWS, NT>>>(im, disp, out);
}

// round 8
// speedup vs baseline: 1.1166x; 1.1166x over previous
#include <cuda_runtime.h>
#include <cuda_fp16.h>

// Problem shape (fixed by the dataset)
#define BATCH 8
#define CHAN  3
#define HH    720
#define WW    1280
#define HW    (HH * WW)
#define NROWS (BATCH * HH)
#define EPSV  1e-6f
#define K_LOG2 0.49978218f     // log2(1.414)

// flow_y == 0 -> 1-D row splat: pixel x hits bins x0=floor(x-d) and x0+1.
// (c0,c1) and (c2,wsum) accumulate as two __half2 shared planes via f16x2
// shared atomics: 4 ATOMS/pixel (payload floor).
//
// R8: XOR bank-hash on the bin->slot map. Blocked mapping makes atomic banks
// (4*lane + k - d) mod 32, clustering lanes {i,i+8,i+16,i+24} on a base bank
// (4*lane mod 32 has only 8 values) -> conflict degree ~3. slot = bin ^
// ((bin>>5)&31) is bijective per 32-word block and XORs the cluster members
// (bins differing by 32/64/96) onto different banks. Readback inverts by
// hashing again.
__device__ __forceinline__ int bhash(int bin) {
    return bin ^ ((bin >> 5) & 31);
}

__global__ __launch_bounds__(320) void splat_kernel(
    const float* __restrict__ im,
    const float* __restrict__ disp,
    float* __restrict__ out)
{
    __shared__ __half2 sA[WW];   // (c0, c1), hashed slots
    __shared__ __half2 sB[WW];   // (c2, w ), hashed slots

    const int row = blockIdx.x;      // b*HH + y
    const int b   = row / HH;
    const int y   = row - b * HH;
    const int tid = threadIdx.x;

    // ---- zero both planes (hash-agnostic) ----
    ((uint4*)sA)[tid] = make_uint4(0u, 0u, 0u, 0u);
    ((uint4*)sB)[tid] = make_uint4(0u, 0u, 0u, 0u);
    __syncthreads();

    const float4* d_row4 = (const float4*)(disp + (size_t)row * WW);
    const float*  im_row = im  + (size_t)b * CHAN * HW + (size_t)y * WW;
    float*        o_row  = out + (size_t)b * CHAN * HW + (size_t)y * WW;

    // ---- splat phase: 4 consecutive pixels per thread ----
    const int xb = tid * 4;
    float4 d4 = d_row4[tid];
    float4 c0 = ((const float4*)(im_row))[tid];
    float4 c1 = ((const float4*)(im_row + HW))[tid];
    float4 c2 = ((const float4*)(im_row + 2 * HW))[tid];

    const float dd[4] = {d4.x, d4.y, d4.z, d4.w};
    const float p0[4] = {c0.x, c0.y, c0.z, c0.w};
    const float p1[4] = {c1.x, c1.y, c1.z, c1.w};
    const float p2[4] = {c2.x, c2.y, c2.z, c2.w};

    #pragma unroll
    for (int k = 0; k < 4; k++) {
        float d = dd[k];
        float w;
        asm("ex2.approx.f32 %0, %1;" : "=f"(w) : "f"(d * K_LOG2));
        float tx  = (float)(xb + k) - d;
        int   x0  = __float2int_rd(tx);
        float fc  = tx - (float)x0;   // weight toward x0+1
        float wc  = w * fc;           // combined weight at x0+1
        float wa  = w - wc;           // combined weight at x0

        float v0 = p0[k], v1 = p1[k], v2 = p2[k];

        if ((unsigned)x0 < WW) {      // x0 in [x-21, x]
            int h0 = bhash(x0);
            atomicAdd(&sA[h0], __floats2half2_rn(v0 * wa, v1 * wa));
            atomicAdd(&sB[h0], __floats2half2_rn(v2 * wa, wa));
        }
        int x1 = x0 + 1;
        if ((unsigned)x1 < WW) {
            int h1 = bhash(x1);
            atomicAdd(&sA[h1], __floats2half2_rn(v0 * wc, v1 * wc));
            atomicAdd(&sB[h1], __floats2half2_rn(v2 * wc, wc));
        }
    }
    __syncthreads();

    // ---- normalize phase: hashed scalar LDS, float4 writes ----
    // bins xb..xb+3 lie in one 32-word block -> common xor value
    const int xorv = (xb >> 5) & 31;
    unsigned va[4], vb[4];
    #pragma unroll
    for (int j = 0; j < 4; j++) {
        int s = (xb + j) ^ xorv;
        va[j] = *(const unsigned*)&sA[s];
        vb[j] = *(const unsigned*)&sB[s];
    }

    float4 r0, r1, r2;
    float* r0p = &r0.x; float* r1p = &r1.x; float* r2p = &r2.x;
    #pragma unroll
    for (int j = 0; j < 4; j++) {
        __half2 a  = *(const __half2*)&va[j];
        __half2 bb = *(const __half2*)&vb[j];
        float n0 = __low2float(a),  n1 = __high2float(a);
        float n2 = __low2float(bb), ws = __high2float(bb);
        float inv;
        asm("rcp.approx.f32 %0, %1;" : "=f"(inv) : "f"(fmaxf(ws, EPSV)));
        r0p[j] = n0 * inv;
        r1p[j] = n1 * inv;
        r2p[j] = n2 * inv;
    }
    ((float4*)o_row)[tid]            = r0;
    ((float4*)(o_row + HW))[tid]     = r1;
    ((float4*)(o_row + 2 * HW))[tid] = r2;
}

extern "C" void kernel_launch(void* const* d_in, const int* in_sizes, int n_in,
                              void* d_out, int out_size) {
    const float* im   = (const float*)d_in[0];   // [8,3,720,1280] fp32
    const float* disp = (const float*)d_in[1];   // [8,1,720,1280] fp32
    float* out = (float*)d_out;                  // [8,3,720,1280] fp32

    splat_kernel<<<NROWS, 320>>>(im, disp, out);
}

// round 9
// speedup vs baseline: 1.1194x; 1.0025x over previous
#include <cuda_runtime.h>
#include <cuda_fp16.h>

// Problem shape (fixed by the dataset)
#define BATCH 8
#define CHAN  3
#define HH    720
#define WW    1280
#define HW    (HH * WW)
#define NROWS (BATCH * HH)
#define EPSV  1e-6f
#define K_LOG2 0.49978218f     // log2(1.414)

// flow_y == 0 -> 1-D row splat: pixel x hits bins x0=floor(x-d) and x0+1.
// (c0,c1) and (c2,wsum) accumulate as two __half2 shared planes via f16x2
// shared atomics: 4 ATOMS/pixel (hard payload floor: 8 f16 halves/pixel,
// shared atomics are 32-bit).
//
// Measured across 4 mapping variants: l1tex busy is invariant (~52.6us) ->
// shared atomics are LANE-rate bound (~2 RMW lanes/cyc/SM), not conflict
// bound. So keep the cheap hash for issue efficiency but make readback free:
// hash only bits [2:5): slot = bin ^ ((bin>>5) & 28). Aligned 4-bin groups
// stay contiguous and ordered -> normalize phase reads plain uint4.
__device__ __forceinline__ int bhash(int bin) {
    return bin ^ ((bin >> 5) & 28);
}

__global__ __launch_bounds__(320) void splat_kernel(
    const float* __restrict__ im,
    const float* __restrict__ disp,
    float* __restrict__ out)
{
    __shared__ __half2 sA[WW];   // (c0, c1), hashed slots
    __shared__ __half2 sB[WW];   // (c2, w ), hashed slots

    const int row = blockIdx.x;      // b*HH + y
    const int b   = row / HH;
    const int y   = row - b * HH;
    const int tid = threadIdx.x;

    // ---- zero both planes (hash-agnostic) ----
    ((uint4*)sA)[tid] = make_uint4(0u, 0u, 0u, 0u);
    ((uint4*)sB)[tid] = make_uint4(0u, 0u, 0u, 0u);
    __syncthreads();

    const float4* d_row4 = (const float4*)(disp + (size_t)row * WW);
    const float*  im_row = im  + (size_t)b * CHAN * HW + (size_t)y * WW;
    float*        o_row  = out + (size_t)b * CHAN * HW + (size_t)y * WW;

    // ---- splat phase: 4 consecutive pixels per thread ----
    const int xb = tid * 4;
    float4 d4 = d_row4[tid];
    float4 c0 = ((const float4*)(im_row))[tid];
    float4 c1 = ((const float4*)(im_row + HW))[tid];
    float4 c2 = ((const float4*)(im_row + 2 * HW))[tid];

    const float dd[4] = {d4.x, d4.y, d4.z, d4.w};
    const float p0[4] = {c0.x, c0.y, c0.z, c0.w};
    const float p1[4] = {c1.x, c1.y, c1.z, c1.w};
    const float p2[4] = {c2.x, c2.y, c2.z, c2.w};

    #pragma unroll
    for (int k = 0; k < 4; k++) {
        float d = dd[k];
        float w;
        asm("ex2.approx.f32 %0, %1;" : "=f"(w) : "f"(d * K_LOG2));
        float tx  = (float)(xb + k) - d;
        int   x0  = __float2int_rd(tx);
        float fc  = tx - (float)x0;   // weight toward x0+1
        float wc  = w * fc;           // combined weight at x0+1
        float wa  = w - wc;           // combined weight at x0

        float v0 = p0[k], v1 = p1[k], v2 = p2[k];

        if ((unsigned)x0 < WW) {      // x0 in [x-21, x]
            int h0 = bhash(x0);
            atomicAdd(&sA[h0], __floats2half2_rn(v0 * wa, v1 * wa));
            atomicAdd(&sB[h0], __floats2half2_rn(v2 * wa, wa));
        }
        int x1 = x0 + 1;
        if ((unsigned)x1 < WW) {
            int h1 = bhash(x1);
            atomicAdd(&sA[h1], __floats2half2_rn(v0 * wc, v1 * wc));
            atomicAdd(&sB[h1], __floats2half2_rn(v2 * wc, wc));
        }
    }
    __syncthreads();

    // ---- normalize phase ----
    // bins xb..xb+3 share one hash xor (bits>=5 identical) which only flips
    // bits 2..4 -> the 4 slots are contiguous and ordered: one uint4 each.
    const int g = (xb ^ ((xb >> 5) & 28)) >> 2;
    uint4 ua = ((const uint4*)sA)[g];   // 4 pixels of (c0,c1)
    uint4 ub = ((const uint4*)sB)[g];   // 4 pixels of (c2,w)
    const unsigned va[4] = {ua.x, ua.y, ua.z, ua.w};
    const unsigned vb[4] = {ub.x, ub.y, ub.z, ub.w};

    float4 r0, r1, r2;
    float* r0p = &r0.x; float* r1p = &r1.x; float* r2p = &r2.x;
    #pragma unroll
    for (int j = 0; j < 4; j++) {
        __half2 a  = *(const __half2*)&va[j];
        __half2 bb = *(const __half2*)&vb[j];
        float n0 = __low2float(a),  n1 = __high2float(a);
        float n2 = __low2float(bb), ws = __high2float(bb);
        float inv;
        asm("rcp.approx.f32 %0, %1;" : "=f"(inv) : "f"(fmaxf(ws, EPSV)));
        r0p[j] = n0 * inv;
        r1p[j] = n1 * inv;
        r2p[j] = n2 * inv;
    }
    ((float4*)o_row)[tid]            = r0;
    ((float4*)(o_row + HW))[tid]     = r1;
    ((float4*)(o_row + 2 * HW))[tid] = r2;
}

extern "C" void kernel_launch(void* const* d_in, const int* in_sizes, int n_in,
                              void* d_out, int out_size) {
    const float* im   = (const float*)d_in[0];   // [8,3,720,1280] fp32
    const float* disp = (const float*)d_in[1];   // [8,1,720,1280] fp32
    float* out = (float*)d_out;                  // [8,3,720,1280] fp32

    splat_kernel<<<NROWS, 320>>>(im, disp, out);
}

// round 10
// speedup vs baseline: 1.2334x; 1.1018x over previous
#include <cuda_runtime.h>
#include <cuda_fp16.h>

// Problem shape (fixed by the dataset)
#define BATCH 8
#define CHAN  3
#define HH    720
#define WW    1280
#define HW    (HH * WW)
#define NROWS (BATCH * HH)
#define EPSV  1e-6f
#define K_LOG2 0.49978218f     // log2(1.414)

// flow_y == 0 -> 1-D row splat: pixel x hits bins x0=floor(x-d) and x0+1.
// (c0,c1) and (c2,wsum) accumulate as two __half2 shared planes.
//
// R10: force return-free shared reductions (red.shared.add.noftz.f16x2).
// Five mapping variants all measured identical l1tex busy (~52.5us): the
// pipe cost is per atomic op, not conflicts. If atomicAdd was compiling to
// ATOMS (result + scoreboard), RED removes the return path. Payloads are
// packed up front so the 16 REDs per thread issue back-to-back with no
// dependencies.
//
// Bank hash (bits [2:5)): slot = bin ^ ((bin>>5)&28); aligned 4-bin groups
// stay contiguous -> uint4 readback.
__device__ __forceinline__ int bhash(int bin) {
    return bin ^ ((bin >> 5) & 28);
}

__device__ __forceinline__ void red_sh_h2(unsigned addr, unsigned val) {
    asm volatile("red.shared.add.noftz.f16x2 [%0], %1;"
                 :: "r"(addr), "r"(val) : "memory");
}

__device__ __forceinline__ unsigned pack_h2(float a, float b) {
    __half2 h = __floats2half2_rn(a, b);
    return *(unsigned*)&h;
}

__global__ __launch_bounds__(320) void splat_kernel(
    const float* __restrict__ im,
    const float* __restrict__ disp,
    float* __restrict__ out)
{
    __shared__ __half2 sA[WW];   // (c0, c1), hashed slots
    __shared__ __half2 sB[WW];   // (c2, w ), hashed slots

    const int row = blockIdx.x;      // b*HH + y
    const int b   = row / HH;
    const int y   = row - b * HH;
    const int tid = threadIdx.x;

    const unsigned baseA = (unsigned)__cvta_generic_to_shared(sA);
    const unsigned baseB = (unsigned)__cvta_generic_to_shared(sB);

    // ---- zero both planes ----
    ((uint4*)sA)[tid] = make_uint4(0u, 0u, 0u, 0u);
    ((uint4*)sB)[tid] = make_uint4(0u, 0u, 0u, 0u);
    __syncthreads();

    const float4* d_row4 = (const float4*)(disp + (size_t)row * WW);
    const float*  im_row = im  + (size_t)b * CHAN * HW + (size_t)y * WW;
    float*        o_row  = out + (size_t)b * CHAN * HW + (size_t)y * WW;

    // ---- splat phase: 4 consecutive pixels per thread ----
    const int xb = tid * 4;
    float4 d4 = d_row4[tid];
    float4 c0 = ((const float4*)(im_row))[tid];
    float4 c1 = ((const float4*)(im_row + HW))[tid];
    float4 c2 = ((const float4*)(im_row + 2 * HW))[tid];

    const float dd[4] = {d4.x, d4.y, d4.z, d4.w};
    const float p0[4] = {c0.x, c0.y, c0.z, c0.w};
    const float p1[4] = {c1.x, c1.y, c1.z, c1.w};
    const float p2[4] = {c2.x, c2.y, c2.z, c2.w};

    // precompute all payloads/addresses, then fire REDs (no return deps)
    unsigned adrA[8], adrB[8], valA[8], valB[8];
    bool ok[8];

    #pragma unroll
    for (int k = 0; k < 4; k++) {
        float d = dd[k];
        float w;
        asm("ex2.approx.f32 %0, %1;" : "=f"(w) : "f"(d * K_LOG2));
        float tx  = (float)(xb + k) - d;
        int   x0  = __float2int_rd(tx);
        float fc  = tx - (float)x0;   // weight toward x0+1
        float wc  = w * fc;           // combined weight at x0+1
        float wa  = w - wc;           // combined weight at x0

        float v0 = p0[k], v1 = p1[k], v2 = p2[k];

        int h0 = bhash(x0);
        int h1 = bhash(x0 + 1);
        ok[2 * k]     = (unsigned)x0 < WW;        // x0 in [x-21, x]
        ok[2 * k + 1] = (unsigned)(x0 + 1) < WW;
        adrA[2 * k]     = baseA + 4u * h0;
        adrB[2 * k]     = baseB + 4u * h0;
        adrA[2 * k + 1] = baseA + 4u * h1;
        adrB[2 * k + 1] = baseB + 4u * h1;
        valA[2 * k]     = pack_h2(v0 * wa, v1 * wa);
        valB[2 * k]     = pack_h2(v2 * wa, wa);
        valA[2 * k + 1] = pack_h2(v0 * wc, v1 * wc);
        valB[2 * k + 1] = pack_h2(v2 * wc, wc);
    }

    #pragma unroll
    for (int i = 0; i < 8; i++) {
        if (ok[i]) {
            red_sh_h2(adrA[i], valA[i]);
            red_sh_h2(adrB[i], valB[i]);
        }
    }
    __syncthreads();

    // ---- normalize phase ----
    // bins xb..xb+3 share one hash xor which only flips bits 2..4 -> the 4
    // slots are contiguous and ordered: one uint4 per plane.
    const int g = (xb ^ ((xb >> 5) & 28)) >> 2;
    uint4 ua = ((const uint4*)sA)[g];   // 4 pixels of (c0,c1)
    uint4 ub = ((const uint4*)sB)[g];   // 4 pixels of (c2,w)
    const unsigned va[4] = {ua.x, ua.y, ua.z, ua.w};
    const unsigned vb[4] = {ub.x, ub.y, ub.z, ub.w};

    float4 r0, r1, r2;
    float* r0p = &r0.x; float* r1p = &r1.x; float* r2p = &r2.x;
    #pragma unroll
    for (int j = 0; j < 4; j++) {
        __half2 a  = *(const __half2*)&va[j];
        __half2 bb = *(const __half2*)&vb[j];
        float n0 = __low2float(a),  n1 = __high2float(a);
        float n2 = __low2float(bb), ws = __high2float(bb);
        float inv;
        asm("rcp.approx.f32 %0, %1;" : "=f"(inv) : "f"(fmaxf(ws, EPSV)));
        r0p[j] = n0 * inv;
        r1p[j] = n1 * inv;
        r2p[j] = n2 * inv;
    }
    ((float4*)o_row)[tid]            = r0;
    ((float4*)(o_row + HW))[tid]     = r1;
    ((float4*)(o_row + 2 * HW))[tid] = r2;
}

extern "C" void kernel_launch(void* const* d_in, const int* in_sizes, int n_in,
                              void* d_out, int out_size) {
    const float* im   = (const float*)d_in[0];   // [8,3,720,1280] fp32
    const float* disp = (const float*)d_in[1];   // [8,1,720,1280] fp32
    float* out = (float*)d_out;                  // [8,3,720,1280] fp32

    splat_kernel<<<NROWS, 320>>>(im, disp, out);
}